// round 9
// baseline (speedup 1.0000x reference)
#include <cuda_runtime.h>

#define R  5
#define KW 11
#define BW 32
#define TILE_H 8
#define TLW 42
#define TLH 18
#define TLSZ (TLH*TLW)
#define H 256
#define W 256
#define CHW (H*W)

// K_i = -0.5 * (1/sigma_i) * log2(e): weight = ex2(sum K_i (g_i - c_i)^2)
#define CA (-0.07213475204444817f)   // sigma 10.0  (ch 0,1)
#define CB (-36.06737602222409f)     // sigma 0.02  (ch 2,3,4)
#define CC (-7.213475204444817f)     // sigma 0.1   (ch 5,6,7)
#define MASKNEG (-1.0e4f)            // ex2(-1e4) flushes to 0

typedef unsigned long long ull;

__device__ __forceinline__ float ex2f(float x) {
    float y;
    asm("ex2.approx.ftz.f32 %0, %1;" : "=f"(y) : "f"(x));
    return y;
}
__device__ __forceinline__ ull pk2(float lo, float hi) {
    ull r; asm("mov.b64 %0, {%1, %2};" : "=l"(r) : "f"(lo), "f"(hi)); return r;
}
__device__ __forceinline__ void upk(ull v, float& lo, float& hi) {
    asm("mov.b64 {%0, %1}, %2;" : "=f"(lo), "=f"(hi) : "l"(v));
}
__device__ __forceinline__ ull mulx2(ull a, ull b) {
    ull r; asm("mul.rn.f32x2 %0, %1, %2;" : "=l"(r) : "l"(a), "l"(b)); return r;
}
__device__ __forceinline__ ull fmax2(ull a, ull b, ull c) {
    ull r; asm("fma.rn.f32x2 %0, %1, %2, %3;" : "=l"(r) : "l"(a), "l"(b), "l"(c)); return r;
}
__device__ __forceinline__ ull d2u(double d) { return __double_as_longlong(d); }

__device__ __forceinline__ int refl(int i, int n) {
    if (i < 0)  i = -i;
    if (i >= n) i = 2*n - 2 - i;
    return i;
}

__global__ __launch_bounds__(256, 3)
void jbf_kernel(const float* __restrict__ img,
                const float* __restrict__ gd,
                float* __restrict__ out)
{
    // sg0 | sg1 | si, pool reused for the h-reduction after compute
    __shared__ float4 pool[3 * TLSZ];
    float4* sg0 = pool;
    float4* sg1 = pool + TLSZ;
    float4* si  = pool + 2 * TLSZ;   // (p.x, p.y, p.z, S)

    const int b   = blockIdx.z;
    const int tx0 = blockIdx.x * BW;
    const int ty0 = blockIdx.y * TILE_H;

    const float* gb = gd  + (size_t)b * 8 * CHW;
    const float* ib = img + (size_t)b * 3 * CHW;

    const int tid = threadIdx.y * BW + threadIdx.x;

    // Halo load with reflect padding; S(g) = sum K_i g_i^2 in si.w
    for (int i = tid; i < TLSZ; i += 256) {
        int ly = i / TLW;
        int lxx = i - ly * TLW;
        int gy = refl(ty0 + ly - R, H);
        int gx = refl(tx0 + lxx - R, W);
        int off = gy * W + gx;
        float g0 = gb[off],         g1 = gb[CHW   + off];
        float g2 = gb[2*CHW + off], g3 = gb[3*CHW + off];
        float g4 = gb[4*CHW + off], g5 = gb[5*CHW + off];
        float g6 = gb[6*CHW + off], g7 = gb[7*CHW + off];
        sg0[i] = make_float4(g0, g1, g2, g3);
        sg1[i] = make_float4(g4, g5, g6, g7);
        float S;
        S =      (CA*g0)*g0;
        S = fmaf( CA*g1, g1, S);
        S = fmaf( CB*g2, g2, S);
        S = fmaf( CB*g3, g3, S);
        S = fmaf( CB*g4, g4, S);
        S = fmaf( CC*g5, g5, S);
        S = fmaf( CC*g6, g6, S);
        S = fmaf( CC*g7, g7, S);
        si[i] = make_float4(ib[off], ib[CHW + off], ib[2*CHW + off], S);
    }
    __syncthreads();

    const int lx  = threadIdx.x;
    const int ty  = threadIdx.y;      // 0..7
    const int g   = ty & 1;           // quad: rows g*4 .. g*4+3 of the tile
    const int h   = ty >> 1;          // 0..3: neighbor-row group
    const int lyb = g * 4;

    // Per-pixel constants: m_j(g) = S(g) + dot(u_j, g) + T_j
    ull u01[4], u23[4], u45[4], u67[4];
    float T[4];
    #pragma unroll
    for (int j = 0; j < 4; ++j) {
        const float4 c0 = sg0[(lyb + j + R) * TLW + lx + R];
        const float4 c1 = sg1[(lyb + j + R) * TLW + lx + R];
        u01[j] = pk2(-2.0f*CA*c0.x, -2.0f*CA*c0.y);
        u23[j] = pk2(-2.0f*CB*c0.z, -2.0f*CB*c0.w);
        u45[j] = pk2(-2.0f*CB*c1.x, -2.0f*CC*c1.y);
        u67[j] = pk2(-2.0f*CC*c1.z, -2.0f*CC*c1.w);
        float t;
        t =      (CA*c0.x)*c0.x;
        t = fmaf( CA*c0.y, c0.y, t);
        t = fmaf( CB*c0.z, c0.z, t);
        t = fmaf( CB*c0.w, c0.w, t);
        t = fmaf( CB*c1.x, c1.x, t);
        t = fmaf( CC*c1.y, c1.y, t);
        t = fmaf( CC*c1.z, c1.z, t);
        t = fmaf( CC*c1.w, c1.w, t);
        T[j] = t;
    }

    float ax[4] = {0,0,0,0}, ay[4] = {0,0,0,0};
    float az[4] = {0,0,0,0}, ws[4] = {0,0,0,0};

    // Row groups over the 14-row union: h0: e=0..3, h1: 4..6, h2: 7..9, h3: 10..13.
    // Neighbor row e serves pixel j iff j <= e <= j+10; masked pixels get T -> -1e4.
    const int estart = (h == 0) ? 0 : (h == 1) ? 4 : (h == 2) ? 7 : 10;
    const int ecount = (h == 1 || h == 2) ? 3 : 4;

    #pragma unroll 1
    for (int k = 0; k < ecount; ++k) {
        const int e = estart + k;
        float Tm0 = (e <= 10)           ? T[0] : MASKNEG;
        float Tm1 = (e >= 1 && e <= 11) ? T[1] : MASKNEG;
        float Tm2 = (e >= 2 && e <= 12) ? T[2] : MASKNEG;
        float Tm3 = (e >= 3)            ? T[3] : MASKNEG;
        float Tm[4] = {Tm0, Tm1, Tm2, Tm3};

        const double2* r0 = (const double2*)(sg0 + (lyb + e) * TLW + lx);
        const double2* r1 = (const double2*)(sg1 + (lyb + e) * TLW + lx);
        const float4*  rp = si + (lyb + e) * TLW + lx;

        #pragma unroll
        for (int dx = 0; dx < KW; ++dx) {
            double2 G0 = r0[dx], G1 = r1[dx];
            float4  P  = rp[dx];
            ull g01 = d2u(G0.x), g23 = d2u(G0.y);
            ull g45 = d2u(G1.x), g67 = d2u(G1.y);

            #pragma unroll
            for (int j = 0; j < 4; ++j) {
                ull t = mulx2(g01, u01[j]);
                t = fmax2(g23, u23[j], t);
                t = fmax2(g45, u45[j], t);
                t = fmax2(g67, u67[j], t);
                float lo, hi; upk(t, lo, hi);
                float w = ex2f((P.w + Tm[j]) + (lo + hi));
                ax[j] = fmaf(w, P.x, ax[j]);
                ay[j] = fmaf(w, P.y, ay[j]);
                az[j] = fmaf(w, P.z, az[j]);
                ws[j] += w;
            }
        }
    }

    // Reduce the 4 h-groups: reuse the tile smem (all tile reads are done)
    __syncthreads();
    float4* red = pool;
    const int quad = g * BW + lx;     // 0..63
    if (h != 0) {
        #pragma unroll
        for (int j = 0; j < 4; ++j)
            red[((h - 1) * 64 + quad) * 4 + j] =
                make_float4(ax[j], ay[j], az[j], ws[j]);
    }
    __syncthreads();

    if (h == 0) {
        #pragma unroll
        for (int j = 0; j < 4; ++j) {
            float sx = ax[j], sy = ay[j], sz = az[j], sw = ws[j];
            #pragma unroll
            for (int q = 0; q < 3; ++q) {
                float4 r = red[(q * 64 + quad) * 4 + j];
                sx += r.x; sy += r.y; sz += r.z; sw += r.w;
            }
            const int oy = ty0 + lyb + j;
            const int ox = tx0 + lx;
            float* ob = out + (size_t)b * 3 * CHW + oy * W + ox;
            const float inv = 1.0f / sw;
            ob[0]     = sx * inv;
            ob[CHW]   = sy * inv;
            ob[2*CHW] = sz * inv;
        }
    }
}

extern "C" void kernel_launch(void* const* d_in, const int* in_sizes, int n_in,
                              void* d_out, int out_size)
{
    const float* img = (const float*)d_in[0];   // (2,3,256,256)
    const float* gd  = (const float*)d_in[1];   // (2,8,256,256)
    float* out = (float*)d_out;                 // (2,3,256,256)

    dim3 block(BW, 8);
    dim3 grid(W / BW, H / TILE_H, 2);
    jbf_kernel<<<grid, block>>>(img, gd, out);
}

// round 10
// speedup vs baseline: 1.0977x; 1.0977x over previous
#include <cuda_runtime.h>

#define R  5
#define KW 11
#define BW 32
#define TILE_H 8
#define PY 2
#define TLW (BW + 2*R)        // 42
#define TLH (TILE_H + 2*R)    // 18
#define H 256
#define W 256
#define CHW (H*W)

// K_i = -0.5 * (1/sigma_i) * log2(e): weight = ex2(sum K_i (g_i - c_i)^2)
#define CA (-0.07213475204444817f)   // sigma 10.0  (ch 0,1)
#define CB (-36.06737602222409f)     // sigma 0.02  (ch 2,3,4)
#define CC (-7.213475204444817f)     // sigma 0.1   (ch 5,6,7)

typedef unsigned long long ull;

__device__ __forceinline__ float ex2f(float x) {
    float y;
    asm("ex2.approx.ftz.f32 %0, %1;" : "=f"(y) : "f"(x));
    return y;
}
__device__ __forceinline__ ull pk2(float lo, float hi) {
    ull r; asm("mov.b64 %0, {%1, %2};" : "=l"(r) : "f"(lo), "f"(hi)); return r;
}
__device__ __forceinline__ void upk(ull v, float& lo, float& hi) {
    asm("mov.b64 {%0, %1}, %2;" : "=f"(lo), "=f"(hi) : "l"(v));
}
__device__ __forceinline__ ull addx2(ull a, ull b) {
    ull r; asm("add.rn.f32x2 %0, %1, %2;" : "=l"(r) : "l"(a), "l"(b)); return r;
}
__device__ __forceinline__ ull fmax2(ull a, ull b, ull c) {
    ull r; asm("fma.rn.f32x2 %0, %1, %2, %3;" : "=l"(r) : "l"(a), "l"(b), "l"(c)); return r;
}
__device__ __forceinline__ ull d2u(double d) { return __double_as_longlong(d); }
__device__ __forceinline__ float hadd(ull v) {
    float lo, hi; upk(v, lo, hi); return lo + hi;
}

__device__ __forceinline__ int refl(int i, int n) {
    if (i < 0)  i = -i;
    if (i >= n) i = 2*n - 2 - i;
    return i;
}

__global__ __launch_bounds__(256, 3)
void jbf_kernel(const float* __restrict__ img,
                const float* __restrict__ gd,
                float* __restrict__ out)
{
    __shared__ float4 sg0[TLH][TLW];
    __shared__ float4 sg1[TLH][TLW];
    __shared__ float4 si [TLH][TLW];    // (p.x, p.y, p.z, S)
    __shared__ float4 redA[4][BW];
    __shared__ float4 redB[4][BW];

    const int b   = blockIdx.z;
    const int tx0 = blockIdx.x * BW;
    const int ty0 = blockIdx.y * TILE_H;

    const float* gb = gd  + (size_t)b * 8 * CHW;
    const float* ib = img + (size_t)b * 3 * CHW;

    const int tid = threadIdx.y * BW + threadIdx.x;

    // Halo load with reflect padding; S(g) = sum K_i g_i^2 stored in si.w
    for (int i = tid; i < TLH * TLW; i += 256) {
        int ly = i / TLW;
        int lxx = i - ly * TLW;
        int gy = refl(ty0 + ly - R, H);
        int gx = refl(tx0 + lxx - R, W);
        int off = gy * W + gx;
        float g0 = gb[off],         g1 = gb[CHW   + off];
        float g2 = gb[2*CHW + off], g3 = gb[3*CHW + off];
        float g4 = gb[4*CHW + off], g5 = gb[5*CHW + off];
        float g6 = gb[6*CHW + off], g7 = gb[7*CHW + off];
        sg0[ly][lxx] = make_float4(g0, g1, g2, g3);
        sg1[ly][lxx] = make_float4(g4, g5, g6, g7);
        float S;
        S =      (CA*g0)*g0;
        S = fmaf( CA*g1, g1, S);
        S = fmaf( CB*g2, g2, S);
        S = fmaf( CB*g3, g3, S);
        S = fmaf( CB*g4, g4, S);
        S = fmaf( CC*g5, g5, S);
        S = fmaf( CC*g6, g6, S);
        S = fmaf( CC*g7, g7, S);
        si[ly][lxx] = make_float4(ib[off], ib[CHW + off], ib[2*CHW + off], S);
    }
    __syncthreads();

    const int lx   = threadIdx.x;
    const int ty   = threadIdx.y;     // 0..7
    const int half = ty >> 2;         // 0: e in 0..5,  1: e in 6..11
    const int g    = ty & 3;          // pixel-pair group 0..3
    const int lyb  = g * PY;          // tile row of pixel A; B = lyb+1

    // m_X(g) = S(g) + dot(u_X, g) + T_X
    ull uA01, uA23, uA45, uA67, TA;   // TA packed (T, 0)
    ull uB01, uB23, uB45, uB67, TB;
    {
        const float4 c0a = sg0[lyb + R][lx + R];
        const float4 c1a = sg1[lyb + R][lx + R];
        uA01 = pk2(-2.0f*CA*c0a.x, -2.0f*CA*c0a.y);
        uA23 = pk2(-2.0f*CB*c0a.z, -2.0f*CB*c0a.w);
        uA45 = pk2(-2.0f*CB*c1a.x, -2.0f*CC*c1a.y);
        uA67 = pk2(-2.0f*CC*c1a.z, -2.0f*CC*c1a.w);
        float t;
        t =      (CA*c0a.x)*c0a.x;
        t = fmaf( CA*c0a.y, c0a.y, t);
        t = fmaf( CB*c0a.z, c0a.z, t);
        t = fmaf( CB*c0a.w, c0a.w, t);
        t = fmaf( CB*c1a.x, c1a.x, t);
        t = fmaf( CC*c1a.y, c1a.y, t);
        t = fmaf( CC*c1a.z, c1a.z, t);
        t = fmaf( CC*c1a.w, c1a.w, t);
        TA = pk2(t, 0.0f);

        const float4 c0b = sg0[lyb + R + 1][lx + R];
        const float4 c1b = sg1[lyb + R + 1][lx + R];
        uB01 = pk2(-2.0f*CA*c0b.x, -2.0f*CA*c0b.y);
        uB23 = pk2(-2.0f*CB*c0b.z, -2.0f*CB*c0b.w);
        uB45 = pk2(-2.0f*CB*c1b.x, -2.0f*CC*c1b.y);
        uB67 = pk2(-2.0f*CC*c1b.z, -2.0f*CC*c1b.w);
        t =      (CA*c0b.x)*c0b.x;
        t = fmaf( CA*c0b.y, c0b.y, t);
        t = fmaf( CB*c0b.z, c0b.z, t);
        t = fmaf( CB*c0b.w, c0b.w, t);
        t = fmaf( CB*c1b.x, c1b.x, t);
        t = fmaf( CC*c1b.y, c1b.y, t);
        t = fmaf( CC*c1b.z, c1b.z, t);
        TB = pk2(t, 0.0f);
    }

    // Accumulators: (ax,ay) packed; az, ws scalar
    ull   aA = pk2(0.0f, 0.0f), aB = aA;
    float azA = 0.0f, wsA = 0.0f, azB = 0.0f, wsB = 0.0f;

    // Dual rows: 5 per half (half0: e=1..5, half1: e=6..10)
    const int ebase = half ? 6 : 1;
    #pragma unroll 1
    for (int k = 0; k < 5; ++k) {
        const int e = ebase + k;
        const double2* r0 = (const double2*)&sg0[lyb + e][lx];
        const double2* r1 = (const double2*)&sg1[lyb + e][lx];
        const double2* rp = (const double2*)&si [lyb + e][lx];
        #pragma unroll
        for (int dx = 0; dx < KW; ++dx) {
            double2 G0 = r0[dx], G1 = r1[dx], P = rp[dx];
            ull g01 = d2u(G0.x), g23 = d2u(G0.y);
            ull g45 = d2u(G1.x), g67 = d2u(G1.y);
            ull p01 = d2u(P.x);
            float pz, S; upk(d2u(P.y), pz, S);

            ull tA = fmax2(g01, uA01, TA);
            tA = fmax2(g23, uA23, tA);
            tA = fmax2(g45, uA45, tA);
            tA = fmax2(g67, uA67, tA);
            float mA = S + hadd(tA);

            ull tB = fmax2(g01, uB01, TB);
            tB = fmax2(g23, uB23, tB);
            tB = fmax2(g45, uB45, tB);
            tB = fmax2(g67, uB67, tB);
            float mB = S + hadd(tB);

            float wA = ex2f(mA);
            float wB = ex2f(mB);

            aA  = fmax2(pk2(wA, wA), p01, aA);
            azA = fmaf(wA, pz, azA);
            wsA += wA;
            aB  = fmax2(pk2(wB, wB), p01, aB);
            azB = fmaf(wB, pz, azB);
            wsB += wB;
        }
    }

    // Single rows: half0 does e=0 (pixel A), half1 does e=11 (pixel B)
    {
        const int e = half ? 11 : 0;
        const ull u01 = half ? uB01 : uA01;
        const ull u23 = half ? uB23 : uA23;
        const ull u45 = half ? uB45 : uA45;
        const ull u67 = half ? uB67 : uA67;
        const ull Tk  = half ? TB   : TA;

        const double2* r0 = (const double2*)&sg0[lyb + e][lx];
        const double2* r1 = (const double2*)&sg1[lyb + e][lx];
        const double2* rp = (const double2*)&si [lyb + e][lx];
        ull   a  = pk2(0.0f, 0.0f);
        float az = 0.0f, ws = 0.0f;
        #pragma unroll
        for (int dx = 0; dx < KW; ++dx) {
            double2 G0 = r0[dx], G1 = r1[dx], P = rp[dx];
            ull t = fmax2(d2u(G0.x), u01, Tk);
            t = fmax2(d2u(G0.y), u23, t);
            t = fmax2(d2u(G1.x), u45, t);
            t = fmax2(d2u(G1.y), u67, t);
            float pz, S; upk(d2u(P.y), pz, S);
            float w = ex2f(S + hadd(t));
            a  = fmax2(pk2(w, w), d2u(P.x), a);
            az = fmaf(w, pz, az);
            ws += w;
        }
        if (half) { aB = addx2(aB, a); azB += az; wsB += ws; }
        else      { aA = addx2(aA, a); azA += az; wsA += ws; }
    }

    float axA, ayA, axB, ayB;
    upk(aA, axA, ayA);
    upk(aB, axB, ayB);

    __syncthreads();
    if (half == 1) {
        redA[g][lx] = make_float4(axA, ayA, azA, wsA);
        redB[g][lx] = make_float4(axB, ayB, azB, wsB);
    }
    __syncthreads();

    if (half == 0) {
        float4 rA = redA[g][lx];
        float4 rB = redB[g][lx];
        axA += rA.x; ayA += rA.y; azA += rA.z; wsA += rA.w;
        axB += rB.x; ayB += rB.y; azB += rB.z; wsB += rB.w;

        const int oy0 = ty0 + lyb;
        const int ox  = tx0 + lx;
        float* ob = out + (size_t)b * 3 * CHW + oy0 * W + ox;

        const float invA = 1.0f / wsA;
        ob[0]     = axA * invA;
        ob[CHW]   = ayA * invA;
        ob[2*CHW] = azA * invA;

        const float invB = 1.0f / wsB;
        ob[W]         = axB * invB;
        ob[CHW + W]   = ayB * invB;
        ob[2*CHW + W] = azB * invB;
    }
}

extern "C" void kernel_launch(void* const* d_in, const int* in_sizes, int n_in,
                              void* d_out, int out_size)
{
    const float* img = (const float*)d_in[0];   // (2,3,256,256)
    const float* gd  = (const float*)d_in[1];   // (2,8,256,256)
    float* out = (float*)d_out;                 // (2,3,256,256)

    dim3 block(BW, 8);
    dim3 grid(W / BW, H / TILE_H, 2);
    jbf_kernel<<<grid, block>>>(img, gd, out);
}